// round 1
// baseline (speedup 1.0000x reference)
#include <cuda_runtime.h>
#include <cuda_bf16.h>

// yoloLoss: pred/target (4096,14,14,30) fp32 -> scalar loss/batch.
// HBM-bound streaming reduction: 192.7 MB read. Two-pass deterministic reduce.

#define S_GRID 14.0f
#define L_COORD 5.0f
#define L_NOOBJ 0.5f
#define N_CH 30
#define BATCH 4096

#define NBLK 784
#define NTHR 256

__device__ float g_partials[NBLK];

__device__ __forceinline__ float iou_box(
    const float* __restrict__ p, const float* __restrict__ t)
{
    // p,t: [x,y,w,h] ; xyxy: xy/S +- 0.5*wh
    const float invS = 1.0f / S_GRID;
    float px1 = p[0] * invS - 0.5f * p[2];
    float py1 = p[1] * invS - 0.5f * p[3];
    float px2 = p[0] * invS + 0.5f * p[2];
    float py2 = p[1] * invS + 0.5f * p[3];
    float tx1 = t[0] * invS - 0.5f * t[2];
    float ty1 = t[1] * invS - 0.5f * t[3];
    float tx2 = t[0] * invS + 0.5f * t[2];
    float ty2 = t[1] * invS + 0.5f * t[3];

    float lx = fmaxf(px1, tx1);
    float ly = fmaxf(py1, ty1);
    float rx = fminf(px2, tx2);
    float ry = fminf(py2, ty2);
    float iw = fmaxf(rx - lx, 0.0f);
    float ih = fmaxf(ry - ly, 0.0f);
    float inter = iw * ih;
    float a1 = (px2 - px1) * (py2 - py1);
    float a2 = (tx2 - tx1) * (ty2 - ty1);
    return inter / (a1 + a2 - inter);
}

__global__ __launch_bounds__(NTHR)
void yolo_loss_partial(const float* __restrict__ pred,
                       const float* __restrict__ targ,
                       int ncells)
{
    int tid = blockIdx.x * blockDim.x + threadIdx.x;
    int stride = gridDim.x * blockDim.x;

    float acc = 0.0f;

    for (int n = tid; n < ncells; n += stride) {
        float p[N_CH], t[N_CH];
        const float2* p2 = reinterpret_cast<const float2*>(pred + (size_t)n * N_CH);
        const float2* t2 = reinterpret_cast<const float2*>(targ + (size_t)n * N_CH);
#pragma unroll
        for (int i = 0; i < N_CH / 2; i++) {
            float2 v = __ldg(p2 + i);
            p[2 * i] = v.x; p[2 * i + 1] = v.y;
        }
#pragma unroll
        for (int i = 0; i < N_CH / 2; i++) {
            float2 v = __ldg(t2 + i);
            t[2 * i] = v.x; t[2 * i + 1] = v.y;
        }

        float m = (t[4] > 0.0f) ? 1.0f : 0.0f;
        float nm = 1.0f - m;

        // IoU of each pred box vs target box 0
        float iou0 = iou_box(p + 0, t + 0);
        float iou1 = iou_box(p + 5, t + 0);
        int off = (iou1 > iou0) ? 5 : 0;      // argmax, ties -> box 0
        float max_iou = fmaxf(iou0, iou1);

        const float* pr = p + off;
        const float* tr = t + off;

        // xy loss
        float dx = pr[0] - tr[0];
        float dy = pr[1] - tr[1];
        float loss_xy = dx * dx + dy * dy;

        // wh loss (sqrt space)
        float dw = sqrtf(pr[2]) - sqrtf(tr[2]);
        float dh = sqrtf(pr[3]) - sqrtf(tr[3]);
        float loss_wh = dw * dw + dh * dh;

        // obj loss
        float dobj = pr[4] - max_iou;
        float loss_obj = dobj * dobj;

        // class loss (channels 10..29)
        float loss_class = 0.0f;
#pragma unroll
        for (int c = 10; c < N_CH; c++) {
            float d = p[c] - t[c];
            loss_class = fmaf(d, d, loss_class);
        }

        // noobj loss: both boxes' conf vs target conf
        float d0 = p[4] - t[4];
        float d1 = p[9] - t[9];
        float loss_noobj = d0 * d0 + d1 * d1;

        acc += m * (L_COORD * (loss_xy + loss_wh) + loss_obj + loss_class)
             + nm * (L_NOOBJ * loss_noobj);
    }

    // warp reduce
#pragma unroll
    for (int o = 16; o > 0; o >>= 1)
        acc += __shfl_down_sync(0xFFFFFFFFu, acc, o);

    __shared__ float smem[NTHR / 32];
    int lane = threadIdx.x & 31;
    int wid = threadIdx.x >> 5;
    if (lane == 0) smem[wid] = acc;
    __syncthreads();
    if (wid == 0) {
        float v = (lane < NTHR / 32) ? smem[lane] : 0.0f;
#pragma unroll
        for (int o = 4; o > 0; o >>= 1)
            v += __shfl_down_sync(0xFFFFFFFFu, v, o);
        if (lane == 0) g_partials[blockIdx.x] = v;
    }
}

__global__ __launch_bounds__(256)
void yolo_loss_finalize(float* __restrict__ out)
{
    __shared__ float smem[8];
    float acc = 0.0f;
    for (int i = threadIdx.x; i < NBLK; i += 256)
        acc += g_partials[i];
#pragma unroll
    for (int o = 16; o > 0; o >>= 1)
        acc += __shfl_down_sync(0xFFFFFFFFu, acc, o);
    int lane = threadIdx.x & 31;
    int wid = threadIdx.x >> 5;
    if (lane == 0) smem[wid] = acc;
    __syncthreads();
    if (wid == 0) {
        float v = (lane < 8) ? smem[lane] : 0.0f;
#pragma unroll
        for (int o = 4; o > 0; o >>= 1)
            v += __shfl_down_sync(0xFFFFFFFFu, v, o);
        if (lane == 0) out[0] = v * (1.0f / (float)BATCH);
    }
}

extern "C" void kernel_launch(void* const* d_in, const int* in_sizes, int n_in,
                              void* d_out, int out_size)
{
    const float* pred = (const float*)d_in[0];
    const float* targ = (const float*)d_in[1];
    float* out = (float*)d_out;

    int ncells = in_sizes[0] / N_CH;   // 4096*14*14 = 802816

    yolo_loss_partial<<<NBLK, NTHR>>>(pred, targ, ncells);
    yolo_loss_finalize<<<1, 256>>>(out);
}

// round 2
// speedup vs baseline: 1.0307x; 1.0307x over previous
#include <cuda_runtime.h>
#include <cuda_bf16.h>

// yoloLoss: pred/target (4096,14,14,30) fp32 -> scalar.
// Coalesced float4 staging into padded SMEM (stride 31 -> conflict-free reads),
// per-cell compute from SMEM, fused last-block finalize. DRAM-bound target.

#define S_GRID   14.0f
#define BATCH    4096
#define NTHR     256
#define TILE     256                   // cells per block
#define NTILES   3136                  // 802816 / 256
#define WPT      (TILE * 30)           // 7680 words per tile per tensor
#define V4PT     (WPT / 4)             // 1920 float4 per tile per tensor
#define PADSTR   31                    // padded words per cell (gcd(31,32)=1)
#define SMEM_F   (TILE * PADSTR)       // 7936 floats per tensor
#define SMEM_BYTES (2 * SMEM_F * 4)    // 63488 B

__device__ float        g_partials[NTILES];
__device__ unsigned int g_done;        // zero-init; reset by last block each launch

__device__ __forceinline__ float iou_one(
    float px, float py, float pw, float ph,
    float tx, float ty, float tw, float th)
{
    const float invS = 1.0f / S_GRID;
    float px1 = px * invS - 0.5f * pw, px2 = px * invS + 0.5f * pw;
    float py1 = py * invS - 0.5f * ph, py2 = py * invS + 0.5f * ph;
    float tx1 = tx * invS - 0.5f * tw, tx2 = tx * invS + 0.5f * tw;
    float ty1 = ty * invS - 0.5f * th, ty2 = ty * invS + 0.5f * th;
    float iw = fmaxf(fminf(px2, tx2) - fmaxf(px1, tx1), 0.0f);
    float ih = fmaxf(fminf(py2, ty2) - fmaxf(py1, ty1), 0.0f);
    float inter = iw * ih;
    float a1 = (px2 - px1) * (py2 - py1);
    float a2 = (tx2 - tx1) * (ty2 - ty1);
    return inter / (a1 + a2 - inter);
}

__device__ __forceinline__ void stage_tensor(
    const float4* __restrict__ src, float* __restrict__ dst, int tid)
{
    float4 v[8];
#pragma unroll
    for (int it = 0; it < 8; it++) {
        int j = tid + it * NTHR;
        if (j < V4PT) v[it] = __ldcg(src + j);
    }
#pragma unroll
    for (int it = 0; it < 8; it++) {
        int j = tid + it * NTHR;
        if (j < V4PT) {
            int w = 4 * j;
            float vals[4] = {v[it].x, v[it].y, v[it].z, v[it].w};
#pragma unroll
            for (int k = 0; k < 4; k++) {
                int ww   = w + k;
                int cell = ww / 30;
                int ch   = ww - cell * 30;
                dst[cell * PADSTR + ch] = vals[k];
            }
        }
    }
}

__global__ __launch_bounds__(NTHR, 3)
void yolo_loss_kernel(const float* __restrict__ pred,
                      const float* __restrict__ targ,
                      float* __restrict__ out)
{
    extern __shared__ float smem[];
    float* sp = smem;
    float* st = smem + SMEM_F;

    const int tid  = threadIdx.x;
    const int tile = blockIdx.x;

    stage_tensor(reinterpret_cast<const float4*>(pred) + (size_t)tile * V4PT, sp, tid);
    stage_tensor(reinterpret_cast<const float4*>(targ) + (size_t)tile * V4PT, st, tid);
    __syncthreads();

    // ---- per-cell compute (thread tid owns cell tid) ----
    const float* cp = sp + tid * PADSTR;
    const float* ct = st + tid * PADSTR;

    float px = cp[0], py = cp[1], pw = cp[2], ph = cp[3], pc0 = cp[4];
    float qx = cp[5], qy = cp[6], qw = cp[7], qh = cp[8], pc1 = cp[9];
    float tx = ct[0], ty = ct[1], tw = ct[2], th = ct[3], tc0 = ct[4];
    float ux = ct[5], uy = ct[6], uw = ct[7], uh = ct[8], tc1 = ct[9];

    float m  = (tc0 > 0.0f) ? 1.0f : 0.0f;
    float nm = 1.0f - m;

    float iou0 = iou_one(px, py, pw, ph, tx, ty, tw, th);
    float iou1 = iou_one(qx, qy, qw, qh, tx, ty, tw, th);
    bool  sec  = (iou1 > iou0);            // argmax, tie -> box 0
    float max_iou = fmaxf(iou0, iou1);

    float rx = sec ? qx : px, ry = sec ? qy : py;
    float rw = sec ? qw : pw, rh = sec ? qh : ph;
    float rc = sec ? pc1 : pc0;
    float sx = sec ? ux : tx, sy = sec ? uy : ty;
    float sw = sec ? uw : tw, sh = sec ? uh : th;

    float dx = rx - sx, dy = ry - sy;
    float loss_xy = dx * dx + dy * dy;
    float dw = sqrtf(rw) - sqrtf(sw);
    float dh = sqrtf(rh) - sqrtf(sh);
    float loss_wh = dw * dw + dh * dh;
    float dob = rc - max_iou;
    float loss_obj = dob * dob;

    float loss_class = 0.0f;
#pragma unroll
    for (int c = 10; c < 30; c++) {
        float d = cp[c] - ct[c];
        loss_class = fmaf(d, d, loss_class);
    }

    float d0 = pc0 - tc0, d1 = pc1 - tc1;
    float loss_noobj = d0 * d0 + d1 * d1;

    float acc = m * (5.0f * (loss_xy + loss_wh) + loss_obj + loss_class)
              + nm * (0.5f * loss_noobj);

    // ---- block reduce ----
#pragma unroll
    for (int o = 16; o > 0; o >>= 1)
        acc += __shfl_down_sync(0xFFFFFFFFu, acc, o);

    __shared__ float red[NTHR / 32];
    int lane = tid & 31, wid = tid >> 5;
    if (lane == 0) red[wid] = acc;
    __syncthreads();
    if (wid == 0) {
        float v = (lane < NTHR / 32) ? red[lane] : 0.0f;
#pragma unroll
        for (int o = 4; o > 0; o >>= 1)
            v += __shfl_down_sync(0xFFFFFFFFu, v, o);
        if (lane == 0) g_partials[blockIdx.x] = v;
    }

    // ---- last-block finalize (deterministic: fixed order over g_partials) ----
    __shared__ int is_last;
    if (tid == 0) {
        __threadfence();
        unsigned prev = atomicAdd(&g_done, 1u);
        is_last = (prev == (unsigned)(gridDim.x - 1));
    }
    __syncthreads();
    if (is_last) {
        __threadfence();
        float a = 0.0f;
        for (int i = tid; i < NTILES; i += NTHR)
            a += g_partials[i];
#pragma unroll
        for (int o = 16; o > 0; o >>= 1)
            a += __shfl_down_sync(0xFFFFFFFFu, a, o);
        if (lane == 0) red[wid] = a;
        __syncthreads();
        if (wid == 0) {
            float v = (lane < NTHR / 32) ? red[lane] : 0.0f;
#pragma unroll
            for (int o = 4; o > 0; o >>= 1)
                v += __shfl_down_sync(0xFFFFFFFFu, v, o);
            if (lane == 0) {
                out[0] = v * (1.0f / (float)BATCH);
                g_done = 0;                 // reset for next graph replay
            }
        }
    }
}

extern "C" void kernel_launch(void* const* d_in, const int* in_sizes, int n_in,
                              void* d_out, int out_size)
{
    const float* pred = (const float*)d_in[0];
    const float* targ = (const float*)d_in[1];
    float* out = (float*)d_out;

    cudaFuncSetAttribute(yolo_loss_kernel,
                         cudaFuncAttributeMaxDynamicSharedMemorySize, SMEM_BYTES);
    yolo_loss_kernel<<<NTILES, NTHR, SMEM_BYTES>>>(pred, targ, out);
}

// round 3
// speedup vs baseline: 1.3111x; 1.2720x over previous
#include <cuda_runtime.h>
#include <cuda_bf16.h>
#include <cstdint>

// yoloLoss: pred/target (4096,14,14,30) fp32 -> scalar.
// cp.async.bulk (UBLKCP) double-buffered SMEM pipeline; compute from SMEM;
// deterministic last-block finalize. Target: DRAM-bound ~85%.

#define S_GRID    14.0f
#define BATCH     4096
#define NTHR      128
#define TILE      128                       // cells per tile (== NTHR)
#define CELL_W    30
#define TILE_F    (TILE * CELL_W)           // 3840 floats
#define TILE_B    (TILE_F * 4)              // 15360 bytes (16B multiple)
#define GRID      448
#define TPB       14                        // tiles per block: 448*14*128 = 802816
#define SMEM_DYN  (4 * TILE_B)              // 2 stages x (pred+targ) = 61440 B

__device__ float    g_partials[GRID];
__device__ unsigned g_done;                 // zero-init; reset by last block

__device__ __forceinline__ unsigned smem_u32(const void* p) {
    return (unsigned)__cvta_generic_to_shared(p);
}

__device__ __forceinline__ void mbar_init(void* mbar, unsigned count) {
    asm volatile("mbarrier.init.shared.b64 [%0], %1;"
                 :: "r"(smem_u32(mbar)), "r"(count) : "memory");
}

__device__ __forceinline__ void mbar_expect_tx(void* mbar, unsigned bytes) {
    asm volatile("mbarrier.arrive.expect_tx.shared.b64 _, [%0], %1;"
                 :: "r"(smem_u32(mbar)), "r"(bytes) : "memory");
}

__device__ __forceinline__ void bulk_g2s(void* dst_smem, const void* src_gmem,
                                         unsigned bytes, void* mbar) {
    asm volatile(
        "cp.async.bulk.shared::cluster.global.mbarrier::complete_tx::bytes "
        "[%0], [%1], %2, [%3];"
        :: "r"(smem_u32(dst_smem)), "l"(src_gmem), "r"(bytes),
           "r"(smem_u32(mbar)) : "memory");
}

__device__ __forceinline__ void mbar_wait(void* mbar, unsigned parity) {
    unsigned addr = smem_u32(mbar);
    unsigned done;
    asm volatile(
        "{\n\t.reg .pred p;\n\t"
        "mbarrier.try_wait.parity.acquire.cta.shared::cta.b64 p, [%1], %2;\n\t"
        "selp.b32 %0, 1, 0, p;\n\t}"
        : "=r"(done) : "r"(addr), "r"(parity) : "memory");
    if (!done) {
        asm volatile(
            "{\n\t.reg .pred P1;\n\t"
            "W_%=:\n\t"
            "mbarrier.try_wait.parity.acquire.cta.shared::cta.b64 P1, [%0], %1, 0x989680;\n\t"
            "@P1 bra.uni D_%=;\n\t"
            "bra.uni W_%=;\n\t"
            "D_%=:\n\t}"
            :: "r"(addr), "r"(parity) : "memory");
    }
}

__device__ __forceinline__ float iou_one(
    float px, float py, float pw, float ph,
    float tx, float ty, float tw, float th)
{
    const float invS = 1.0f / S_GRID;
    float px1 = px * invS - 0.5f * pw, px2 = px * invS + 0.5f * pw;
    float py1 = py * invS - 0.5f * ph, py2 = py * invS + 0.5f * ph;
    float tx1 = tx * invS - 0.5f * tw, tx2 = tx * invS + 0.5f * tw;
    float ty1 = ty * invS - 0.5f * th, ty2 = ty * invS + 0.5f * th;
    float iw = fmaxf(fminf(px2, tx2) - fmaxf(px1, tx1), 0.0f);
    float ih = fmaxf(fminf(py2, ty2) - fmaxf(py1, ty1), 0.0f);
    float inter = iw * ih;
    float a1 = (px2 - px1) * (py2 - py1);
    float a2 = (tx2 - tx1) * (ty2 - ty1);
    return inter / (a1 + a2 - inter);
}

__global__ __launch_bounds__(NTHR, 3)
void yolo_loss_kernel(const float* __restrict__ pred,
                      const float* __restrict__ targ,
                      float* __restrict__ out)
{
    extern __shared__ __align__(16) float buf[];   // [2 stages][pred|targ][TILE_F]
    __shared__ __align__(8) unsigned long long mbar[2];
    __shared__ float red[NTHR / 32];
    __shared__ int   is_last;

    const int tid = threadIdx.x;
    const int tile0 = blockIdx.x * TPB;

    if (tid == 0) { mbar_init(&mbar[0], 1); mbar_init(&mbar[1], 1); }
    __syncthreads();

    // prologue: issue tiles 0 and 1
    if (tid == 0) {
#pragma unroll
        for (int i = 0; i < 2; i++) {
            const size_t goff = (size_t)(tile0 + i) * TILE_F;
            float* dp = buf + (size_t)(i * 2 + 0) * TILE_F;
            float* dt = buf + (size_t)(i * 2 + 1) * TILE_F;
            mbar_expect_tx(&mbar[i], 2 * TILE_B);
            bulk_g2s(dp, pred + goff, TILE_B, &mbar[i]);
            bulk_g2s(dt, targ + goff, TILE_B, &mbar[i]);
        }
    }

    float acc = 0.0f;
    int ph0 = 0, ph1 = 0;

    for (int i = 0; i < TPB; i++) {
        const int s = i & 1;
        if (s == 0) { mbar_wait(&mbar[0], ph0); if (i + 2 >= TPB || true) {} }
        else        { mbar_wait(&mbar[1], ph1); }
        // flip parity for next reuse of this stage
        if (s == 0) ph0 ^= 1; else ph1 ^= 1;

        const float* cp = buf + (size_t)(s * 2 + 0) * TILE_F + tid * CELL_W;
        const float* ct = buf + (size_t)(s * 2 + 1) * TILE_F + tid * CELL_W;

        float px = cp[0], py = cp[1], pw = cp[2], ph_ = cp[3], pc0 = cp[4];
        float qx = cp[5], qy = cp[6], qw = cp[7], qh  = cp[8], pc1 = cp[9];
        float tx = ct[0], ty = ct[1], tw = ct[2], th  = ct[3], tc0 = ct[4];
        float ux = ct[5], uy = ct[6], uw = ct[7], uh  = ct[8], tc1 = ct[9];

        float m  = (tc0 > 0.0f) ? 1.0f : 0.0f;
        float nm = 1.0f - m;

        float iou0 = iou_one(px, py, pw, ph_, tx, ty, tw, th);
        float iou1 = iou_one(qx, qy, qw, qh,  tx, ty, tw, th);
        bool  sec  = (iou1 > iou0);            // argmax, tie -> box 0
        float max_iou = fmaxf(iou0, iou1);

        float rx = sec ? qx : px, ry = sec ? qy : py;
        float rw = sec ? qw : pw, rh = sec ? qh : ph_;
        float rc = sec ? pc1 : pc0;
        float sx = sec ? ux : tx, sy = sec ? uy : ty;
        float sw = sec ? uw : tw, sh = sec ? uh : th;

        float dx = rx - sx, dy = ry - sy;
        float loss_xy = dx * dx + dy * dy;
        float dw = sqrtf(rw) - sqrtf(sw);
        float dh = sqrtf(rh) - sqrtf(sh);
        float loss_wh = dw * dw + dh * dh;
        float dob = rc - max_iou;
        float loss_obj = dob * dob;

        float loss_class = 0.0f;
#pragma unroll
        for (int c = 10; c < CELL_W; c++) {
            float d = cp[c] - ct[c];
            loss_class = fmaf(d, d, loss_class);
        }

        float d0 = pc0 - tc0, d1 = pc1 - tc1;
        float loss_noobj = d0 * d0 + d1 * d1;

        acc += m * (5.0f * (loss_xy + loss_wh) + loss_obj + loss_class)
             + nm * (0.5f * loss_noobj);

        __syncthreads();   // everyone done reading stage s

        if (tid == 0 && i + 2 < TPB) {
            const size_t goff = (size_t)(tile0 + i + 2) * TILE_F;
            float* dp = buf + (size_t)(s * 2 + 0) * TILE_F;
            float* dt = buf + (size_t)(s * 2 + 1) * TILE_F;
            mbar_expect_tx(&mbar[s], 2 * TILE_B);
            bulk_g2s(dp, pred + goff, TILE_B, &mbar[s]);
            bulk_g2s(dt, targ + goff, TILE_B, &mbar[s]);
        }
    }

    // ---- block reduce ----
#pragma unroll
    for (int o = 16; o > 0; o >>= 1)
        acc += __shfl_down_sync(0xFFFFFFFFu, acc, o);
    int lane = tid & 31, wid = tid >> 5;
    if (lane == 0) red[wid] = acc;
    __syncthreads();
    if (wid == 0) {
        float v = (lane < NTHR / 32) ? red[lane] : 0.0f;
#pragma unroll
        for (int o = 2; o > 0; o >>= 1)
            v += __shfl_down_sync(0xFFFFFFFFu, v, o);
        if (lane == 0) g_partials[blockIdx.x] = v;
    }

    // ---- deterministic last-block finalize ----
    if (tid == 0) {
        __threadfence();
        unsigned prev = atomicAdd(&g_done, 1u);
        is_last = (prev == (unsigned)(gridDim.x - 1));
    }
    __syncthreads();
    if (is_last) {
        __threadfence();
        float a = 0.0f;
        for (int i = tid; i < GRID; i += NTHR)
            a += g_partials[i];
#pragma unroll
        for (int o = 16; o > 0; o >>= 1)
            a += __shfl_down_sync(0xFFFFFFFFu, a, o);
        if (lane == 0) red[wid] = a;
        __syncthreads();
        if (wid == 0) {
            float v = (lane < NTHR / 32) ? red[lane] : 0.0f;
#pragma unroll
            for (int o = 2; o > 0; o >>= 1)
                v += __shfl_down_sync(0xFFFFFFFFu, v, o);
            if (lane == 0) {
                out[0] = v * (1.0f / (float)BATCH);
                g_done = 0;           // reset for next graph replay
            }
        }
    }
}

extern "C" void kernel_launch(void* const* d_in, const int* in_sizes, int n_in,
                              void* d_out, int out_size)
{
    const float* pred = (const float*)d_in[0];
    const float* targ = (const float*)d_in[1];
    float* out = (float*)d_out;

    cudaFuncSetAttribute(yolo_loss_kernel,
                         cudaFuncAttributeMaxDynamicSharedMemorySize, SMEM_DYN);
    yolo_loss_kernel<<<GRID, NTHR, SMEM_DYN>>>(pred, targ, out);
}

// round 4
// speedup vs baseline: 1.3361x; 1.0190x over previous
#include <cuda_runtime.h>
#include <cuda_bf16.h>
#include <cstdint>

// yoloLoss: pred/target (4096,14,14,30) fp32 -> scalar.
// 3-stage cp.async.bulk (TMA bulk) SMEM pipeline, 2 CTAs/SM, persistent
// strided tiles, deterministic last-block finalize.

#define S_GRID    14.0f
#define BATCH     4096
#define NTHR      128
#define TILE      128                       // cells per tile (== NTHR)
#define CELL_W    30
#define TILE_F    (TILE * CELL_W)           // 3840 floats
#define TILE_B    (TILE_F * 4)              // 15360 bytes
#define STAGES    3
#define GRID      296                       // 2 CTAs/SM on 148 SMs
#define NTILES    6272                      // 802816 / 128
#define SMEM_DYN  (STAGES * 2 * TILE_B)     // 92160 B

__device__ float    g_partials[GRID];
__device__ unsigned g_done;                 // zero-init; reset by last block

__device__ __forceinline__ unsigned smem_u32(const void* p) {
    return (unsigned)__cvta_generic_to_shared(p);
}
__device__ __forceinline__ void mbar_init(void* mbar, unsigned count) {
    asm volatile("mbarrier.init.shared.b64 [%0], %1;"
                 :: "r"(smem_u32(mbar)), "r"(count) : "memory");
}
__device__ __forceinline__ void mbar_expect_tx(void* mbar, unsigned bytes) {
    asm volatile("mbarrier.arrive.expect_tx.shared.b64 _, [%0], %1;"
                 :: "r"(smem_u32(mbar)), "r"(bytes) : "memory");
}
__device__ __forceinline__ void bulk_g2s(void* dst_smem, const void* src_gmem,
                                         unsigned bytes, void* mbar) {
    asm volatile(
        "cp.async.bulk.shared::cluster.global.mbarrier::complete_tx::bytes "
        "[%0], [%1], %2, [%3];"
        :: "r"(smem_u32(dst_smem)), "l"(src_gmem), "r"(bytes),
           "r"(smem_u32(mbar)) : "memory");
}
__device__ __forceinline__ void mbar_wait(void* mbar, unsigned parity) {
    unsigned addr = smem_u32(mbar);
    unsigned done;
    asm volatile(
        "{\n\t.reg .pred p;\n\t"
        "mbarrier.try_wait.parity.acquire.cta.shared::cta.b64 p, [%1], %2;\n\t"
        "selp.b32 %0, 1, 0, p;\n\t}"
        : "=r"(done) : "r"(addr), "r"(parity) : "memory");
    if (!done) {
        asm volatile(
            "{\n\t.reg .pred P1;\n\t"
            "W_%=:\n\t"
            "mbarrier.try_wait.parity.acquire.cta.shared::cta.b64 P1, [%0], %1, 0x989680;\n\t"
            "@P1 bra.uni D_%=;\n\t"
            "bra.uni W_%=;\n\t"
            "D_%=:\n\t}"
            :: "r"(addr), "r"(parity) : "memory");
    }
}

__device__ __forceinline__ float iou_one(
    float px, float py, float pw, float ph,
    float tx, float ty, float tw, float th)
{
    const float invS = 1.0f / S_GRID;
    float px1 = px * invS - 0.5f * pw, px2 = px * invS + 0.5f * pw;
    float py1 = py * invS - 0.5f * ph, py2 = py * invS + 0.5f * ph;
    float tx1 = tx * invS - 0.5f * tw, tx2 = tx * invS + 0.5f * tw;
    float ty1 = ty * invS - 0.5f * th, ty2 = ty * invS + 0.5f * th;
    float iw = fmaxf(fminf(px2, tx2) - fmaxf(px1, tx1), 0.0f);
    float ih = fmaxf(fminf(py2, ty2) - fmaxf(py1, ty1), 0.0f);
    float inter = iw * ih;
    float a1 = (px2 - px1) * (py2 - py1);
    float a2 = (tx2 - tx1) * (ty2 - ty1);
    return inter / (a1 + a2 - inter);
}

__global__ __launch_bounds__(NTHR, 2)
void yolo_loss_kernel(const float* __restrict__ pred,
                      const float* __restrict__ targ,
                      float* __restrict__ out)
{
    extern __shared__ __align__(16) float buf[];   // [STAGES][pred|targ][TILE_F]
    __shared__ __align__(8) unsigned long long mbar[STAGES];
    __shared__ float red[NTHR / 32];
    __shared__ int   is_last;

    const int tid = threadIdx.x;
    const int bid = blockIdx.x;

    // number of tiles this block owns (strided assignment: bid + c*GRID)
    const int nc = (NTILES - bid + GRID - 1) / GRID;

    if (tid == 0) {
#pragma unroll
        for (int s = 0; s < STAGES; s++) mbar_init(&mbar[s], 1);
    }
    __syncthreads();

    // prologue: fill the pipeline
    if (tid == 0) {
#pragma unroll
        for (int k = 0; k < STAGES; k++) {
            if (k < nc) {
                const size_t goff = (size_t)(bid + k * GRID) * TILE_F;
                float* dp = buf + (size_t)(k * 2 + 0) * TILE_F;
                float* dt = buf + (size_t)(k * 2 + 1) * TILE_F;
                mbar_expect_tx(&mbar[k], 2 * TILE_B);
                bulk_g2s(dp, pred + goff, TILE_B, &mbar[k]);
                bulk_g2s(dt, targ + goff, TILE_B, &mbar[k]);
            }
        }
    }

    float acc = 0.0f;

    for (int c = 0; c < nc; c++) {
        const int s = c % STAGES;
        const unsigned parity = (unsigned)((c / STAGES) & 1);
        mbar_wait(&mbar[s], parity);

        const float* cp = buf + (size_t)(s * 2 + 0) * TILE_F + tid * CELL_W;
        const float* ct = buf + (size_t)(s * 2 + 1) * TILE_F + tid * CELL_W;

        float px = cp[0], py = cp[1], pw = cp[2], ph_ = cp[3], pc0 = cp[4];
        float qx = cp[5], qy = cp[6], qw = cp[7], qh  = cp[8], pc1 = cp[9];
        float tx = ct[0], ty = ct[1], tw = ct[2], th  = ct[3], tc0 = ct[4];
        float ux = ct[5], uy = ct[6], uw = ct[7], uh  = ct[8], tc1 = ct[9];

        float m  = (tc0 > 0.0f) ? 1.0f : 0.0f;
        float nm = 1.0f - m;

        float iou0 = iou_one(px, py, pw, ph_, tx, ty, tw, th);
        float iou1 = iou_one(qx, qy, qw, qh,  tx, ty, tw, th);
        bool  sec  = (iou1 > iou0);            // argmax, tie -> box 0
        float max_iou = fmaxf(iou0, iou1);

        float rx = sec ? qx : px, ry = sec ? qy : py;
        float rw = sec ? qw : pw, rh = sec ? qh : ph_;
        float rc = sec ? pc1 : pc0;
        float sx = sec ? ux : tx, sy = sec ? uy : ty;
        float sw = sec ? uw : tw, sh = sec ? uh : th;

        float dx = rx - sx, dy = ry - sy;
        float loss_xy = dx * dx + dy * dy;
        float dw = sqrtf(rw) - sqrtf(sw);
        float dh = sqrtf(rh) - sqrtf(sh);
        float loss_wh = dw * dw + dh * dh;
        float dob = rc - max_iou;
        float loss_obj = dob * dob;

        float loss_class = 0.0f;
#pragma unroll
        for (int ch = 10; ch < CELL_W; ch++) {
            float d = cp[ch] - ct[ch];
            loss_class = fmaf(d, d, loss_class);
        }

        float d0 = pc0 - tc0, d1 = pc1 - tc1;
        float loss_noobj = d0 * d0 + d1 * d1;

        acc += m * (5.0f * (loss_xy + loss_wh) + loss_obj + loss_class)
             + nm * (0.5f * loss_noobj);

        __syncthreads();   // all threads done reading stage s

        if (tid == 0 && c + STAGES < nc) {
            const size_t goff = (size_t)(bid + (c + STAGES) * GRID) * TILE_F;
            float* dp = buf + (size_t)(s * 2 + 0) * TILE_F;
            float* dt = buf + (size_t)(s * 2 + 1) * TILE_F;
            mbar_expect_tx(&mbar[s], 2 * TILE_B);
            bulk_g2s(dp, pred + goff, TILE_B, &mbar[s]);
            bulk_g2s(dt, targ + goff, TILE_B, &mbar[s]);
        }
    }

    // ---- block reduce ----
#pragma unroll
    for (int o = 16; o > 0; o >>= 1)
        acc += __shfl_down_sync(0xFFFFFFFFu, acc, o);
    int lane = tid & 31, wid = tid >> 5;
    if (lane == 0) red[wid] = acc;
    __syncthreads();
    if (wid == 0) {
        float v = (lane < NTHR / 32) ? red[lane] : 0.0f;
#pragma unroll
        for (int o = 2; o > 0; o >>= 1)
            v += __shfl_down_sync(0xFFFFFFFFu, v, o);
        if (lane == 0) g_partials[blockIdx.x] = v;
    }

    // ---- deterministic last-block finalize ----
    if (tid == 0) {
        __threadfence();
        unsigned prev = atomicAdd(&g_done, 1u);
        is_last = (prev == (unsigned)(gridDim.x - 1));
    }
    __syncthreads();
    if (is_last) {
        __threadfence();
        float a = 0.0f;
        for (int i = tid; i < GRID; i += NTHR)
            a += g_partials[i];
#pragma unroll
        for (int o = 16; o > 0; o >>= 1)
            a += __shfl_down_sync(0xFFFFFFFFu, a, o);
        if (lane == 0) red[wid] = a;
        __syncthreads();
        if (wid == 0) {
            float v = (lane < NTHR / 32) ? red[lane] : 0.0f;
#pragma unroll
            for (int o = 2; o > 0; o >>= 1)
                v += __shfl_down_sync(0xFFFFFFFFu, v, o);
            if (lane == 0) {
                out[0] = v * (1.0f / (float)BATCH);
                g_done = 0;           // reset for next graph replay
            }
        }
    }
}

extern "C" void kernel_launch(void* const* d_in, const int* in_sizes, int n_in,
                              void* d_out, int out_size)
{
    const float* pred = (const float*)d_in[0];
    const float* targ = (const float*)d_in[1];
    float* out = (float*)d_out;

    cudaFuncSetAttribute(yolo_loss_kernel,
                         cudaFuncAttributeMaxDynamicSharedMemorySize, SMEM_DYN);
    yolo_loss_kernel<<<GRID, NTHR, SMEM_DYN>>>(pred, targ, out);
}